// round 10
// baseline (speedup 1.0000x reference)
#include <cuda_runtime.h>
#include <cuda_fp16.h>
#include <cstdint>
#include <cstddef>

// ---------------------------------------------------------------- geometry
#define KTOT 12544
#define NOUT 168
#define MTOT 8192
#define KSPLIT 2
#define KPC (KTOT / KSPLIT)       // 6272
#define BM 128
#define BK 32
#define NITER (KPC / BK)          // 196
#define STAGES 4
#define NTHREADS 448              // 14 warps: 7 along N x 2 along M

// A tile: fp32, row stride 36 floats (144B, 16B aligned, bank-staggered)
#define A_ROW_F 36
#define A_TILE_BYTES (BM * A_ROW_F * 4)      // 18432
// B tile: fp16, row = 32 halves (64B data) padded to 80B stride (16B aligned)
#define B_ROW_B 80
#define B_ROW_H 40
#define B_TILE_BYTES (NOUT * B_ROW_B)        // 13440
#define B_OFF A_TILE_BYTES
#define STAGE_BYTES (A_TILE_BYTES + B_TILE_BYTES)   // 31872
#define SMEM_TOTAL (STAGES * STAGE_BYTES)           // 127488
#define CHUNKS_A (BM * 8)                 // 1024 16B chunks
#define CHUNKS_B (NOUT * 4)               // 672
#define CHUNKS_TOT (CHUNKS_A + CHUNKS_B)  // 1696

// output region offsets (cls, reg, face, colour, motion concatenated)
#define OFF_CLS  0
#define OFF_REG  262144
#define OFF_FACE 1277952
#define OFF_COL  1302528
#define OFF_MOT  1359872

__device__ __align__(16) __half g_Wt[(size_t)NOUT * KTOT];   // [n][k], fp16 RN
__device__ __align__(16) float g_partial[(size_t)KSPLIT * MTOT * NOUT];
__device__ float g_bias[NOUT];

// ---------------------------------------------------------------- helpers
__device__ __forceinline__ uint32_t smem_u32(const void* p) {
    uint32_t a;
    asm("{ .reg .u64 t; cvta.to.shared.u64 t, %1; cvt.u32.u64 %0, t; }" : "=r"(a) : "l"(p));
    return a;
}
__device__ __forceinline__ void cp16(uint32_t dst, const void* src) {
    asm volatile("cp.async.cg.shared.global [%0], [%1], 16;" :: "r"(dst), "l"(src) : "memory");
}
__device__ __forceinline__ void cp_commit() {
    asm volatile("cp.async.commit_group;" ::: "memory");
}
template <int N>
__device__ __forceinline__ void cp_wait() {
    asm volatile("cp.async.wait_group %0;" :: "n"(N) : "memory");
}
__device__ __forceinline__ uint32_t pack_h2(float lo, float hi) {
    uint32_t r;
    asm("cvt.rn.f16x2.f32 %0, %1, %2;" : "=r"(r) : "f"(hi), "f"(lo));  // hi into upper, lo into lower
    return r;
}
__device__ __forceinline__ void mma_f16(float* c, const uint32_t* a, const uint32_t* b) {
    asm volatile(
        "mma.sync.aligned.m16n8k16.row.col.f32.f16.f16.f32 "
        "{%0,%1,%2,%3}, {%4,%5,%6,%7}, {%8,%9}, {%0,%1,%2,%3};"
        : "+f"(c[0]), "+f"(c[1]), "+f"(c[2]), "+f"(c[3])
        : "r"(a[0]), "r"(a[1]), "r"(a[2]), "r"(a[3]), "r"(b[0]), "r"(b[1]));
}

// ---------------------------------------------------------------- pack bias
__global__ void pack_bias_kernel(const float* bc, const float* br, const float* bf,
                                 const float* bco, const float* bm) {
    int t = threadIdx.x;
    if (t < 32)       g_bias[t] = bc[t];
    else if (t < 156) g_bias[t] = br[t - 32];
    else if (t < 159) g_bias[t] = bf[t - 156];
    else if (t < 166) g_bias[t] = bco[t - 159];
    else if (t < 168) g_bias[t] = bm[t - 166];
}

// ---------------------------------------------------------------- pack W -> g_Wt[n][k] fp16 (RN, unbiased)
// grid (KTOT/32, 5), block (32, 8)
__global__ void pack_w_kernel(const float* Wc, const float* Wr, const float* Wf,
                              const float* Wco, const float* Wm) {
    __shared__ float tile[32][33];
    const float* srcs[5] = {Wc, Wr, Wf, Wco, Wm};
    const int dims[5] = {32, 124, 3, 7, 2};
    const int offs[5] = {0, 32, 156, 159, 166};
    int s = blockIdx.y;
    const float* src = srcs[s];
    int dim = dims[s], noff = offs[s];
    int kbase = blockIdx.x * 32;
    int tx = threadIdx.x, ty = threadIdx.y;
    int ntiles = (dim + 31) / 32;
    for (int nt = 0; nt < ntiles; nt++) {
        int nbase = nt * 32;
        __syncthreads();
        #pragma unroll
        for (int j = ty; j < 32; j += 8) {
            int k = kbase + j, n = nbase + tx;
            tile[j][tx] = (n < dim) ? src[(size_t)k * dim + n] : 0.0f;
        }
        __syncthreads();
        #pragma unroll
        for (int j = ty; j < 32; j += 8) {
            int n = nbase + j, k = kbase + tx;
            if (n < dim)
                g_Wt[(size_t)(noff + n) * KTOT + k] = __float2half_rn(tile[tx][j]);
        }
    }
}

// ---------------------------------------------------------------- main GEMM
// grid = 128 (64 M-tiles x 2 K-splits), 448 threads, mma.sync m16n8k16 fp16.
__global__ void __launch_bounds__(NTHREADS, 1) gemm_kernel(const float* __restrict__ x) {
    extern __shared__ char smem[];
    uint32_t sb = smem_u32(smem);
    const int tid = threadIdx.x;
    const int lane = tid & 31, wid = tid >> 5;
    const int warpN = wid % 7, warpM = wid / 7;   // 7 x 2
    const int wN0 = warpN * 24, wM0 = warpM * 64;
    const int g = lane >> 2, t = lane & 3;

    const int mtile = blockIdx.x & 63;
    const int ks = blockIdx.x >> 6;
    const int m0 = mtile * BM;
    const int k0 = ks * KPC;

    float c[4][3][4];
    #pragma unroll
    for (int mt = 0; mt < 4; mt++)
        #pragma unroll
        for (int nt = 0; nt < 3; nt++)
            #pragma unroll
            for (int j = 0; j < 4; j++) c[mt][nt][j] = 0.0f;

    // -------- stage loader (cp.async): A fp32 rows, B fp16 rows
    auto load_stage = [&](int stage, int kiter) {
        uint32_t st = sb + stage * STAGE_BYTES;
        int kk = k0 + kiter * BK;
        #pragma unroll 1
        for (int ci = tid; ci < CHUNKS_TOT; ci += NTHREADS) {
            if (ci < CHUNKS_A) {
                int row = ci >> 3, seg = ci & 7;
                cp16(st + row * 144 + seg * 16,
                     x + (size_t)(m0 + row) * KTOT + kk + seg * 4);
            } else {
                int c2 = ci - CHUNKS_A;
                int row = c2 >> 2, seg = c2 & 3;
                cp16(st + B_OFF + row * B_ROW_B + seg * 16,
                     g_Wt + (size_t)row * KTOT + kk + seg * 8);
            }
        }
    };

    #pragma unroll
    for (int s = 0; s < STAGES - 1; s++) { load_stage(s, s); cp_commit(); }

    int stage = 0;
    for (int it = 0; it < NITER; it++) {
        cp_wait<STAGES - 2>();
        __syncthreads();

        int nxt = it + STAGES - 1;
        if (nxt < NITER) load_stage((stage + STAGES - 1) % STAGES, nxt);
        cp_commit();

        const float*  As = (const float*)(smem + stage * STAGE_BYTES);
        const __half* Bs = (const __half*)(smem + stage * STAGE_BYTES + B_OFF);

        #pragma unroll
        for (int k16 = 0; k16 < 2; k16++) {
            const int kb = k16 * 16;
            uint32_t a[4][4], b[3][2];
            #pragma unroll
            for (int mt = 0; mt < 4; mt++) {
                const float* p = As + (wM0 + mt * 16 + g) * A_ROW_F + kb + 2 * t;
                float2 v0 = *reinterpret_cast<const float2*>(p);                    // row g,   k=2t,2t+1
                float2 v1 = *reinterpret_cast<const float2*>(p + 8 * A_ROW_F);      // row g+8
                float2 v2 = *reinterpret_cast<const float2*>(p + 8);                // row g,   k=2t+8,2t+9
                float2 v3 = *reinterpret_cast<const float2*>(p + 8 * A_ROW_F + 8);  // row g+8
                a[mt][0] = pack_h2(v0.x, v0.y);
                a[mt][1] = pack_h2(v1.x, v1.y);
                a[mt][2] = pack_h2(v2.x, v2.y);
                a[mt][3] = pack_h2(v3.x, v3.y);
            }
            #pragma unroll
            for (int nt = 0; nt < 3; nt++) {
                const __half* q = Bs + (wN0 + nt * 8 + g) * B_ROW_H + kb + 2 * t;
                b[nt][0] = *reinterpret_cast<const uint32_t*>(q);        // k=2t,2t+1
                b[nt][1] = *reinterpret_cast<const uint32_t*>(q + 8);    // k=2t+8,2t+9
            }
            #pragma unroll
            for (int mt = 0; mt < 4; mt++)
                #pragma unroll
                for (int nt = 0; nt < 3; nt++)
                    mma_f16(c[mt][nt], a[mt], b[nt]);
        }
        stage = (stage + 1) % STAGES;
        __syncthreads();
    }
    cp_wait<0>();

    // -------- epilogue: partials to g_partial[ks][m][n]
    #pragma unroll
    for (int mt = 0; mt < 4; mt++) {
        #pragma unroll
        for (int nt = 0; nt < 3; nt++) {
            int m = m0 + wM0 + mt * 16 + g;
            int n = wN0 + nt * 8 + 2 * t;
            float* p0 = g_partial + ((size_t)ks * MTOT + m) * NOUT + n;
            *reinterpret_cast<float2*>(p0) = make_float2(c[mt][nt][0], c[mt][nt][1]);
            float* p1 = p0 + (size_t)8 * NOUT;
            *reinterpret_cast<float2*>(p1) = make_float2(c[mt][nt][2], c[mt][nt][3]);
        }
    }
}

// ---------------------------------------------------------------- reduce + bias + scatter
__global__ void reduce_kernel(float* __restrict__ out) {
    int idx = blockIdx.x * 256 + threadIdx.x;
    if (idx >= MTOT * NOUT) return;
    int m = idx / NOUT;
    int n = idx - m * NOUT;
    const size_t STR = (size_t)MTOT * NOUT;
    float s = g_partial[idx] + g_partial[idx + STR] + g_bias[n];
    size_t o;
    if (n < 32)       o = OFF_CLS  + (size_t)m * 32  + n;
    else if (n < 156) o = OFF_REG  + (size_t)m * 124 + (n - 32);
    else if (n < 159) o = OFF_FACE + (size_t)m * 3   + (n - 156);
    else if (n < 166) o = OFF_COL  + (size_t)m * 7   + (n - 159);
    else              o = OFF_MOT  + (size_t)m * 2   + (n - 166);
    out[o] = s;
}

// ---------------------------------------------------------------- launch
extern "C" void kernel_launch(void* const* d_in, const int* in_sizes, int n_in,
                              void* d_out, int out_size) {
    const float* x     = (const float*)d_in[0];
    const float* W_cls = (const float*)d_in[1];
    const float* b_cls = (const float*)d_in[2];
    const float* W_reg = (const float*)d_in[3];
    const float* b_reg = (const float*)d_in[4];
    const float* W_fac = (const float*)d_in[5];
    const float* b_fac = (const float*)d_in[6];
    const float* W_col = (const float*)d_in[7];
    const float* b_col = (const float*)d_in[8];
    const float* W_mot = (const float*)d_in[9];
    const float* b_mot = (const float*)d_in[10];
    float* out = (float*)d_out;

    cudaFuncSetAttribute(gemm_kernel, cudaFuncAttributeMaxDynamicSharedMemorySize, SMEM_TOTAL);

    pack_bias_kernel<<<1, 256>>>(b_cls, b_reg, b_fac, b_col, b_mot);
    pack_w_kernel<<<dim3(KTOT / 32, 5), dim3(32, 8)>>>(W_cls, W_reg, W_fac, W_col, W_mot);
    gemm_kernel<<<128, NTHREADS, SMEM_TOTAL>>>(x);
    reduce_kernel<<<(MTOT * NOUT + 255) / 256, 256>>>(out);
}

// round 14
// speedup vs baseline: 1.1062x; 1.1062x over previous
#include <cuda_runtime.h>
#include <cuda_fp16.h>
#include <cstdint>
#include <cstddef>

// ---------------------------------------------------------------- geometry
#define KTOT 12544
#define NOUT 168
#define MTOT 8192
#define BM 128
#define BK 32
#define NTILES (MTOT / BM)        // 64
#define CPT (KTOT / BK)           // 392 chunks per tile
#define TOTWORK (NTILES * CPT)    // 25088 chunk-units
#define GRID 148
#define STAGES 4
#define NTHREADS 448              // 14 warps: 7 along N x 2 along M

// A tile: fp32, row stride 36 floats (144B)
#define A_ROW_F 36
#define A_TILE_BYTES (BM * A_ROW_F * 4)      // 18432
// B tile: fp16, row = 32 halves padded to 80B stride
#define B_ROW_B 80
#define B_ROW_H 40
#define B_TILE_BYTES (NOUT * B_ROW_B)        // 13440
#define B_OFF A_TILE_BYTES
#define STAGE_BYTES (A_TILE_BYTES + B_TILE_BYTES)   // 31872
#define SMEM_TOTAL (STAGES * STAGE_BYTES)           // 127488
#define CHUNKS_A (BM * 8)                 // 1024 16B chunks
#define CHUNKS_B (NOUT * 4)               // 672
#define CHUNKS_TOT (CHUNKS_A + CHUNKS_B)  // 1696

// output region offsets (cls, reg, face, colour, motion concatenated)
#define OFF_CLS  0
#define OFF_REG  262144
#define OFF_FACE 1277952
#define OFF_COL  1302528
#define OFF_MOT  1359872

__device__ __align__(16) __half g_Wt[(size_t)NOUT * KTOT];            // [n][k], fp16 RN
__device__ __align__(16) float g_partial[(size_t)4 * MTOT * NOUT];    // 4 slots, zero-init
__device__ float g_bias[NOUT];

// ---------------------------------------------------------------- helpers
__device__ __forceinline__ uint32_t smem_u32(const void* p) {
    uint32_t a;
    asm("{ .reg .u64 t; cvta.to.shared.u64 t, %1; cvt.u32.u64 %0, t; }" : "=r"(a) : "l"(p));
    return a;
}
__device__ __forceinline__ void cp16(uint32_t dst, const void* src) {
    asm volatile("cp.async.cg.shared.global [%0], [%1], 16;" :: "r"(dst), "l"(src) : "memory");
}
__device__ __forceinline__ void cp_commit() {
    asm volatile("cp.async.commit_group;" ::: "memory");
}
template <int N>
__device__ __forceinline__ void cp_wait() {
    asm volatile("cp.async.wait_group %0;" :: "n"(N) : "memory");
}
__device__ __forceinline__ uint32_t pack_h2(float lo, float hi) {
    uint32_t r;
    asm("cvt.rn.f16x2.f32 %0, %1, %2;" : "=r"(r) : "f"(hi), "f"(lo));
    return r;
}
__device__ __forceinline__ void mma_f16(float* c, const uint32_t* a, const uint32_t* b) {
    asm volatile(
        "mma.sync.aligned.m16n8k16.row.col.f32.f16.f16.f32 "
        "{%0,%1,%2,%3}, {%4,%5,%6,%7}, {%8,%9}, {%0,%1,%2,%3};"
        : "+f"(c[0]), "+f"(c[1]), "+f"(c[2]), "+f"(c[3])
        : "r"(a[0]), "r"(a[1]), "r"(a[2]), "r"(a[3]), "r"(b[0]), "r"(b[1]));
}

// ---------------------------------------------------------------- pack bias
__global__ void pack_bias_kernel(const float* bc, const float* br, const float* bf,
                                 const float* bco, const float* bm) {
    int t = threadIdx.x;
    if (t < 32)       g_bias[t] = bc[t];
    else if (t < 156) g_bias[t] = br[t - 32];
    else if (t < 159) g_bias[t] = bf[t - 156];
    else if (t < 166) g_bias[t] = bco[t - 159];
    else if (t < 168) g_bias[t] = bm[t - 166];
}

// ---------------------------------------------------------------- pack W -> g_Wt[n][k] fp16 RN
__global__ void pack_w_kernel(const float* Wc, const float* Wr, const float* Wf,
                              const float* Wco, const float* Wm) {
    __shared__ float tile[32][33];
    const float* srcs[5] = {Wc, Wr, Wf, Wco, Wm};
    const int dims[5] = {32, 124, 3, 7, 2};
    const int offs[5] = {0, 32, 156, 159, 166};
    int s = blockIdx.y;
    const float* src = srcs[s];
    int dim = dims[s], noff = offs[s];
    int kbase = blockIdx.x * 32;
    int tx = threadIdx.x, ty = threadIdx.y;
    int ntiles = (dim + 31) / 32;
    for (int nt = 0; nt < ntiles; nt++) {
        int nbase = nt * 32;
        __syncthreads();
        #pragma unroll
        for (int j = ty; j < 32; j += 8) {
            int k = kbase + j, n = nbase + tx;
            tile[j][tx] = (n < dim) ? src[(size_t)k * dim + n] : 0.0f;
        }
        __syncthreads();
        #pragma unroll
        for (int j = ty; j < 32; j += 8) {
            int n = nbase + j, k = kbase + tx;
            if (n < dim)
                g_Wt[(size_t)(noff + n) * KTOT + k] = __float2half_rn(tile[tx][j]);
        }
    }
}

// ---------------------------------------------------------------- main GEMM
// 148 persistent CTAs over a balanced global chunk space (64 tiles x 392 chunks).
__global__ void __launch_bounds__(NTHREADS, 1) gemm_kernel(const float* __restrict__ x) {
    extern __shared__ char smem[];
    uint32_t sb = smem_u32(smem);
    const int tid = threadIdx.x;
    const int lane = tid & 31, wid = tid >> 5;
    const int warpN = wid % 7, warpM = wid / 7;   // 7 x 2
    const int wN0 = warpN * 24, wM0 = warpM * 64;
    const int g = lane >> 2, t = lane & 3;

    const int bid = blockIdx.x;
    const int start = (bid * TOTWORK) / GRID;
    const int end   = ((bid + 1) * TOTWORK) / GRID;
    const int len = end - start;       // 169 or 170
    const int slot = bid & 3;

    float c[4][3][4];
    #pragma unroll
    for (int mt = 0; mt < 4; mt++)
        #pragma unroll
        for (int nt = 0; nt < 3; nt++)
            #pragma unroll
            for (int j = 0; j < 4; j++) c[mt][nt][j] = 0.0f;

    // -------- stage loader: global chunk gc -> (tile, k-chunk)
    auto load_stage = [&](int stage, int gc) {
        int tile = gc / CPT;
        int kk = (gc - tile * CPT) * BK;
        int m0 = tile * BM;
        uint32_t st = sb + stage * STAGE_BYTES;
        #pragma unroll 1
        for (int ci = tid; ci < CHUNKS_TOT; ci += NTHREADS) {
            if (ci < CHUNKS_A) {
                int row = ci >> 3, seg = ci & 7;
                cp16(st + row * 144 + seg * 16,
                     x + (size_t)(m0 + row) * KTOT + kk + seg * 4);
            } else {
                int c2 = ci - CHUNKS_A;
                int row = c2 >> 2, seg = c2 & 3;
                cp16(st + B_OFF + row * B_ROW_B + seg * 16,
                     g_Wt + (size_t)row * KTOT + kk + seg * 8);
            }
        }
    };

    // flush accumulators for tile -> g_partial[slot], then zero them
    auto flush = [&](int tile) {
        int m0 = tile * BM;
        #pragma unroll
        for (int mt = 0; mt < 4; mt++) {
            #pragma unroll
            for (int nt = 0; nt < 3; nt++) {
                int m = m0 + wM0 + mt * 16 + g;
                int n = wN0 + nt * 8 + 2 * t;
                float* p0 = g_partial + ((size_t)slot * MTOT + m) * NOUT + n;
                *reinterpret_cast<float2*>(p0) = make_float2(c[mt][nt][0], c[mt][nt][1]);
                float* p1 = p0 + (size_t)8 * NOUT;
                *reinterpret_cast<float2*>(p1) = make_float2(c[mt][nt][2], c[mt][nt][3]);
                #pragma unroll
                for (int j = 0; j < 4; j++) c[mt][nt][j] = 0.0f;
            }
        }
    };

    #pragma unroll
    for (int s = 0; s < STAGES - 1; s++) {
        if (s < len) load_stage(s, start + s);
        cp_commit();
    }

    int stage = 0;
    for (int it = 0; it < len; it++) {
        const int gc = start + it;
        cp_wait<STAGES - 2>();
        __syncthreads();

        int nxt = it + STAGES - 1;
        if (nxt < len) load_stage((stage + STAGES - 1) % STAGES, start + nxt);
        cp_commit();

        const float*  As = (const float*)(smem + stage * STAGE_BYTES);
        const __half* Bs = (const __half*)(smem + stage * STAGE_BYTES + B_OFF);

        #pragma unroll
        for (int k16 = 0; k16 < 2; k16++) {
            const int kb = k16 * 16;
            uint32_t a[4][4], b[3][2];
            #pragma unroll
            for (int mt = 0; mt < 4; mt++) {
                const float* p = As + (wM0 + mt * 16 + g) * A_ROW_F + kb + 2 * t;
                float2 v0 = *reinterpret_cast<const float2*>(p);
                float2 v1 = *reinterpret_cast<const float2*>(p + 8 * A_ROW_F);
                float2 v2 = *reinterpret_cast<const float2*>(p + 8);
                float2 v3 = *reinterpret_cast<const float2*>(p + 8 * A_ROW_F + 8);
                a[mt][0] = pack_h2(v0.x, v0.y);
                a[mt][1] = pack_h2(v1.x, v1.y);
                a[mt][2] = pack_h2(v2.x, v2.y);
                a[mt][3] = pack_h2(v3.x, v3.y);
            }
            #pragma unroll
            for (int nt = 0; nt < 3; nt++) {
                const __half* q = Bs + (wN0 + nt * 8 + g) * B_ROW_H + kb + 2 * t;
                b[nt][0] = *reinterpret_cast<const uint32_t*>(q);
                b[nt][1] = *reinterpret_cast<const uint32_t*>(q + 8);
            }
            #pragma unroll
            for (int mt = 0; mt < 4; mt++)
                #pragma unroll
                for (int nt = 0; nt < 3; nt++)
                    mma_f16(c[mt][nt], a[mt], b[nt]);
        }
        stage = (stage + 1) % STAGES;
        __syncthreads();

        // flush at tile boundary or range end (register-only, no smem hazard)
        int tile = gc / CPT;
        if (it == len - 1 || (gc + 1) / CPT != tile) flush(tile);
    }
    cp_wait<0>();
}

// ---------------------------------------------------------------- reduce + bias + scatter
__global__ void reduce_kernel(float* __restrict__ out) {
    int idx = blockIdx.x * 256 + threadIdx.x;
    if (idx >= MTOT * NOUT) return;
    int m = idx / NOUT;
    int n = idx - m * NOUT;
    const size_t STR = (size_t)MTOT * NOUT;
    const float* p = g_partial + idx;
    float s = p[0] + p[STR] + p[2 * STR] + p[3 * STR] + g_bias[n];
    size_t o;
    if (n < 32)       o = OFF_CLS  + (size_t)m * 32  + n;
    else if (n < 156) o = OFF_REG  + (size_t)m * 124 + (n - 32);
    else if (n < 159) o = OFF_FACE + (size_t)m * 3   + (n - 156);
    else if (n < 166) o = OFF_COL  + (size_t)m * 7   + (n - 159);
    else              o = OFF_MOT  + (size_t)m * 2   + (n - 166);
    out[o] = s;
}

// ---------------------------------------------------------------- launch
extern "C" void kernel_launch(void* const* d_in, const int* in_sizes, int n_in,
                              void* d_out, int out_size) {
    const float* x     = (const float*)d_in[0];
    const float* W_cls = (const float*)d_in[1];
    const float* b_cls = (const float*)d_in[2];
    const float* W_reg = (const float*)d_in[3];
    const float* b_reg = (const float*)d_in[4];
    const float* W_fac = (const float*)d_in[5];
    const float* b_fac = (const float*)d_in[6];
    const float* W_col = (const float*)d_in[7];
    const float* b_col = (const float*)d_in[8];
    const float* W_mot = (const float*)d_in[9];
    const float* b_mot = (const float*)d_in[10];
    float* out = (float*)d_out;

    cudaFuncSetAttribute(gemm_kernel, cudaFuncAttributeMaxDynamicSharedMemorySize, SMEM_TOTAL);

    pack_bias_kernel<<<1, 256>>>(b_cls, b_reg, b_fac, b_col, b_mot);
    pack_w_kernel<<<dim3(KTOT / 32, 5), dim3(32, 8)>>>(W_cls, W_reg, W_fac, W_col, W_mot);
    gemm_kernel<<<GRID, NTHREADS, SMEM_TOTAL>>>(x);
    reduce_kernel<<<(MTOT * NOUT + 255) / 256, 256>>>(out);
}